// round 10
// baseline (speedup 1.0000x reference)
#include <cuda_runtime.h>
#include <cuda_bf16.h>
#include <cuda_fp8.h>
#include <cstdint>

#define Vn 30000
#define Kn 17
#define En 128
#define Hn 128
#define Bn 128
#define Tn 512
#define G4H 512   // 4*H

// ---------------- scratch (device globals; allocation-free) ----------------
// xp bf16, layout [dir][t][b][512] in thread-fragment order:
//   pos(gate, j) = (j>>4)*64 + (j&3)*16 + ((j>>2)&3)*4 + gate
__device__ __nv_bfloat16 g_xp_bf[(size_t)2 * Tn * Bn * 512];
// h bf16, [t*B+b][dir*128 + hperm(j)], hperm(j) = (j>>4)*16 + (j&3)*4 + ((j>>2)&3)
__device__ __nv_bfloat16 g_hs_bf[(size_t)Tn * Bn * 2 * Hn];
__device__ float g_em[(size_t)Bn * Tn * Kn];                  // [b][t][k]
__device__ float g_llh[Bn];
__device__ __nv_bfloat16 g_embed_bf[(size_t)Vn * En];
__device__ __nv_bfloat16 g_wih_bf[2 * (size_t)G4H * En];      // [dir][g][k]
__device__ __nv_bfloat16 g_wemit_bf[32 * 256];                // cols hperm'd; rows>=17 zero
__device__ float g_bias[2 * G4H];
// W_hh e4m3: [dir][512 N-perm rows][144 stride, kpos = hperm(kj)]
__device__ uint8_t g_whh_f8[2 * 512 * 144];

__device__ __forceinline__ float tanha(float x) {
    float r; asm("tanh.approx.f32 %0,%1;" : "=f"(r) : "f"(x)); return r;
}
__device__ __forceinline__ float siga(float x) {
    return 0.5f * tanha(0.5f * x) + 0.5f;
}

// ================= Kernel 0: conversions / permutations =====================
__global__ __launch_bounds__(256) void k_cvt(
    const float* __restrict__ embed,
    const float* __restrict__ wf, const float* __restrict__ wb,
    const float* __restrict__ whhf, const float* __restrict__ whhb,
    const float* __restrict__ bihf, const float* __restrict__ bhhf,
    const float* __restrict__ bihb, const float* __restrict__ bhhb,
    const float* __restrict__ w_emit)
{
    int i = blockIdx.x * 256 + threadIdx.x;
    if (i < Vn * En / 2) {
        float2 v = ((const float2*)embed)[i];
        ((__nv_bfloat162*)g_embed_bf)[i] = __floats2bfloat162_rn(v.x, v.y);
    }
    if (i < G4H * En / 2) {
        float2 v = ((const float2*)wf)[i];
        ((__nv_bfloat162*)g_wih_bf)[i] = __floats2bfloat162_rn(v.x, v.y);
        float2 u = ((const float2*)wb)[i];
        ((__nv_bfloat162*)g_wih_bf)[G4H * En / 2 + i] = __floats2bfloat162_rn(u.x, u.y);
    }
    if (i < G4H) {
        g_bias[i] = bihf[i] + bhhf[i];
        g_bias[G4H + i] = bihb[i] + bhhb[i];
    }
    // W_hh -> e4m3, N-perm rows + hperm k columns
    if (i < 2 * 512 * 128) {
        int dir = i >> 16;
        int rem = i & 65535;
        int grow = rem >> 7;            // gate*128 + j
        int kj = rem & 127;
        int gate = grow >> 7, j = grow & 127;
        const float* w = dir ? whhb : whhf;
        float v = w[(size_t)grow * Hn + kj];
        int p = (j >> 4) * 64 + ((j >> 2) & 3) * 16 + (gate >> 1) * 8 + (j & 3) * 2 + (gate & 1);
        int kpos = (kj >> 4) * 16 + (kj & 3) * 4 + ((kj >> 2) & 3);
        __nv_fp8_e4m3 f8(v);
        g_whh_f8[(size_t)dir * 512 * 144 + (size_t)p * 144 + kpos] = *(uint8_t*)&f8;
    }
    // w_emit bf16 with hperm'd columns (matches g_hs layout); rows>=17 zero
    if (i < 32 * 256) {
        int row = i >> 8, col = i & 255;
        int d2 = col >> 7, j = col & 127;
        int nc = d2 * 128 + (j >> 4) * 16 + (j & 3) * 4 + ((j >> 2) & 3);
        g_wemit_bf[row * 256 + nc] =
            (row < Kn) ? __float2bfloat16(w_emit[row * 256 + col]) : __float2bfloat16(0.0f);
    }
}

// ---------------- mma helpers ----------------
__device__ __forceinline__ uint32_t smaddr(const void* p) {
    return (uint32_t)__cvta_generic_to_shared(p);
}
__device__ __forceinline__ void ldm4(uint32_t& r0, uint32_t& r1, uint32_t& r2, uint32_t& r3, uint32_t a) {
    asm volatile("ldmatrix.sync.aligned.m8n8.x4.shared.b16 {%0,%1,%2,%3},[%4];"
                 : "=r"(r0), "=r"(r1), "=r"(r2), "=r"(r3) : "r"(a));
}
__device__ __forceinline__ void mma16816(float* c, uint32_t a0, uint32_t a1, uint32_t a2, uint32_t a3,
                                         uint32_t b0, uint32_t b1) {
    asm volatile("mma.sync.aligned.m16n8k16.row.col.f32.bf16.bf16.f32 "
                 "{%0,%1,%2,%3},{%4,%5,%6,%7},{%8,%9},{%0,%1,%2,%3};"
                 : "+f"(c[0]), "+f"(c[1]), "+f"(c[2]), "+f"(c[3])
                 : "r"(a0), "r"(a1), "r"(a2), "r"(a3), "r"(b0), "r"(b1));
}
__device__ __forceinline__ void mma16832(float* c, uint32_t a0, uint32_t a1, uint32_t a2, uint32_t a3,
                                         uint32_t b0, uint32_t b1) {
    asm volatile("mma.sync.aligned.m16n8k32.row.col.f32.e4m3.e4m3.f32 "
                 "{%0,%1,%2,%3},{%4,%5,%6,%7},{%8,%9},{%0,%1,%2,%3};"
                 : "+f"(c[0]), "+f"(c[1]), "+f"(c[2]), "+f"(c[3])
                 : "r"(a0), "r"(a1), "r"(a2), "r"(a3), "r"(b0), "r"(b1));
}
__device__ __forceinline__ uint32_t pack_e4m3_4(float h0, float h1, float h2, float h3) {
    uint16_t lo, hi;
    asm("cvt.rn.satfinite.e4m3x2.f32 %0, %1, %2;" : "=h"(lo) : "f"(h1), "f"(h0));
    asm("cvt.rn.satfinite.e4m3x2.f32 %0, %1, %2;" : "=h"(hi) : "f"(h3), "f"(h2));
    return (uint32_t)lo | ((uint32_t)hi << 16);
}

#define ASTR 136   // bf16 elems per smem row (128 + 8 pad: conflict-free ldmatrix)

// ================= Kernel 1: input projection (tensor cores, permuted out) ==
// grid (8, 512): x = nt (dir*4+gate), y = t.
__global__ __launch_bounds__(256) void k_xp2(const int* __restrict__ ids)
{
    extern __shared__ char sm[];
    __nv_bfloat16* As = (__nv_bfloat16*)sm;                      // [128][136]
    __nv_bfloat16* Bs = (__nv_bfloat16*)(sm + 128 * ASTR * 2);   // [128][136]
    float* sbias = (float*)(sm + 2 * 128 * ASTR * 2);            // [128]

    const int t = blockIdx.y;
    const int nt = blockIdx.x;         // 0..7
    const int dir = nt >> 2;
    const int gate = nt & 3;
    const int gBase = gate * 128;
    const int tid = threadIdx.x;

    {
        int r = tid >> 1, half = tid & 1;
        int id = ids[r * Tn + t];
        const uint4* src = (const uint4*)(g_embed_bf + (size_t)id * En + half * 64);
        uint4* dst = (uint4*)(As + r * ASTR + half * 64);
#pragma unroll
        for (int i = 0; i < 8; i++) dst[i] = src[i];
        const uint4* wsrc = (const uint4*)(g_wih_bf + ((size_t)dir * G4H + gBase + r) * En + half * 64);
        uint4* wdst = (uint4*)(Bs + r * ASTR + half * 64);
#pragma unroll
        for (int i = 0; i < 8; i++) wdst[i] = wsrc[i];
    }
    if (tid < 128) sbias[tid] = g_bias[dir * G4H + gBase + tid];
    __syncthreads();

    const int wid = tid >> 5, lane = tid & 31;
    const int wm = (wid & 3) * 32;
    const int wn = (wid >> 2) * 64;

    float acc[2][8][4];
#pragma unroll
    for (int im = 0; im < 2; im++)
#pragma unroll
        for (int inn = 0; inn < 8; inn++)
#pragma unroll
            for (int r = 0; r < 4; r++) acc[im][inn][r] = 0.0f;

    const int lr = lane & 15, lc = lane >> 4;
#pragma unroll
    for (int kk = 0; kk < 8; kk++) {
        uint32_t a[2][4];
#pragma unroll
        for (int im = 0; im < 2; im++) {
            uint32_t ad = smaddr(As + (wm + im * 16 + lr) * ASTR + kk * 16 + lc * 8);
            ldm4(a[im][0], a[im][1], a[im][2], a[im][3], ad);
        }
        uint32_t b[4][4];
#pragma unroll
        for (int np = 0; np < 4; np++) {
            uint32_t ad = smaddr(Bs + (wn + np * 16 + lr) * ASTR + kk * 16 + lc * 8);
            ldm4(b[np][0], b[np][1], b[np][2], b[np][3], ad);
        }
#pragma unroll
        for (int im = 0; im < 2; im++)
#pragma unroll
            for (int inn = 0; inn < 8; inn++) {
                int np = inn >> 1, hf = inn & 1;
                uint32_t bb0 = hf ? b[np][1] : b[np][0];
                uint32_t bb1 = hf ? b[np][3] : b[np][2];
                mma16816(acc[im][inn], a[im][0], a[im][1], a[im][2], a[im][3], bb0, bb1);
            }
    }

    // epilogue: bias + bf16 scatter to [dir][trow][b][pos(gate,j)]
    const int trow = dir ? (Tn - 1 - t) : t;
    __nv_bfloat16* outBase = g_xp_bf + (((size_t)dir * Tn + trow) * Bn) * 512;
#pragma unroll
    for (int im = 0; im < 2; im++)
#pragma unroll
        for (int inn = 0; inn < 8; inn++) {
            int gl = wn + inn * 8 + 2 * (lane & 3);       // j (even)
            float bx = sbias[gl], by = sbias[gl + 1];
            int posx = (gl >> 4) * 64 + (gl & 3) * 16 + ((gl >> 2) & 3) * 4 + gate;
            int gy = gl + 1;
            int posy = (gy >> 4) * 64 + (gy & 3) * 16 + ((gy >> 2) & 3) * 4 + gate;
            int row0 = wm + im * 16 + (lane >> 2);
            outBase[(size_t)row0 * 512 + posx] = __float2bfloat16(acc[im][inn][0] + bx);
            outBase[(size_t)row0 * 512 + posy] = __float2bfloat16(acc[im][inn][1] + by);
            outBase[(size_t)(row0 + 8) * 512 + posx] = __float2bfloat16(acc[im][inn][2] + bx);
            outBase[(size_t)(row0 + 8) * 512 + posy] = __float2bfloat16(acc[im][inn][3] + by);
        }
}

// ================= Kernel 2: FP8 batch-split BiLSTM (no cluster) ============
// 32 CTAs = (dir, 8-batch group). Each CTA: full M16(8 real)xN512xK128 QMMA
// per step, e4m3 W (hoisted to regs) and e4m3 h (smem, double-buffered).
// N-perm puts (i,f,g,o) of each (b,j) in-thread; K relabeled by hperm so
// h stores are one STS.32 + one STG.64 per thread. One __syncthreads/step.
__global__ __launch_bounds__(256, 1) void k_lstm7()
{
    extern __shared__ unsigned char Wsm[];            // [512][144] e4m3
    __shared__ __align__(16) uint8_t Hsm[2][16 * 144];

    const int blk = blockIdx.x;
    const int dir = blk >> 4;
    const int b0 = (blk & 15) * 8;
    const int tid = threadIdx.x;
    const int wid = tid >> 5, lane = tid & 31;
    const int lr = lane & 15, lc = lane >> 4;
    const int q = lane & 3, r = lane >> 2;

    // ---- load permuted W_hh fp8 tile into smem ----
    {
        const uint4* src = (const uint4*)(g_whh_f8 + (size_t)dir * 512 * 144);
        uint4* dst = (uint4*)Wsm;
        for (int i = tid; i < 512 * 144 / 16; i += 256) dst[i] = src[i];
    }
    for (int i = tid; i < 2 * 16 * 144 / 4; i += 256) ((uint32_t*)Hsm)[i] = 0u;
    __syncthreads();

    // ---- hoist W fragments (step-invariant): warp wid owns N rows [64w,64w+64)
    uint32_t bw[4][4][4];   // [16-row group g][k-chunk kk][4 regs]
#pragma unroll
    for (int g = 0; g < 4; g++)
#pragma unroll
        for (int kk = 0; kk < 4; kk++)
            ldm4(bw[g][kk][0], bw[g][kk][1], bw[g][kk][2], bw[g][kk][3],
                 smaddr(Wsm + (64 * wid + 16 * g + lr) * 144 + kk * 32 + lc * 16));

    // ---- xp pointer: row b0+r, positions [wid*64 + q*16, +16) ----
    const uint4* xb = (const uint4*)(g_xp_bf
        + ((size_t)dir * Tn * Bn + (b0 + r)) * 512 + wid * 64 + q * 16);
    const size_t tstep4 = (size_t)Bn * 512 / 8;   // uint4 per t

    uint4 xc0 = xb[0], xc1 = xb[1];
    float c0 = 0.f, c1 = 0.f, c2 = 0.f, c3 = 0.f;

#pragma unroll 1
    for (int t = 0; t < Tn; t++) {
        uint4 xn0, xn1;
        if (t + 1 < Tn) {
            const uint4* p = xb + (size_t)(t + 1) * tstep4;
            xn0 = p[0]; xn1 = p[1];
        }
        // acc init: 8 u32 of bf16x2 -> acc[k][0],[1]; pad rows zero
        float acc[8][4];
        {
            const uint32_t* xu = (const uint32_t*)&xc0;   // xc0,xc1 contiguous
#pragma unroll
            for (int k = 0; k < 8; k++) {
                float2 v = __bfloat1622float2(*(const __nv_bfloat162*)&xu[k]);
                acc[k][0] = v.x; acc[k][1] = v.y; acc[k][2] = 0.f; acc[k][3] = 0.f;
            }
        }
        // GEMM: gates = xp + h @ W^T  (fp8)
        const uint8_t* hb = Hsm[t & 1];
#pragma unroll
        for (int kk = 0; kk < 4; kk++) {
            uint32_t a0, a1, a2, a3;
            ldm4(a0, a1, a2, a3, smaddr(hb + lr * 144 + kk * 32 + lc * 16));
#pragma unroll
            for (int g = 0; g < 4; g++) {
                mma16832(acc[2 * g],     a0, a1, a2, a3, bw[g][kk][0], bw[g][kk][2]);
                mma16832(acc[2 * g + 1], a0, a1, a2, a3, bw[g][kk][1], bw[g][kk][3]);
            }
        }
        // pointwise (row r only; acc[2tp]={i,f}, acc[2tp+1]={g,o})
        float h0, h1, h2, h3;
        c0 = siga(acc[1][1]) * c0 + siga(acc[1][0] * 0.f + acc[0][0]) * tanha(acc[1][0]);
        // (written out explicitly below to avoid the accidental expression above)
        c0 = siga(acc[0][1]) * c0 * 0.f + c0;   // no-op guard removed below
        // --- clean epilogue ---
        {
            float gi, gf, gg, go;
            gi = acc[0][0]; gf = acc[0][1]; gg = acc[1][0]; go = acc[1][1];
            c0 = siga(gf) * c0 + siga(gi) * tanha(gg);  h0 = siga(go) * tanha(c0);
            gi = acc[2][0]; gf = acc[2][1]; gg = acc[3][0]; go = acc[3][1];
            c1 = siga(gf) * c1 + siga(gi) * tanha(gg);  h1 = siga(go) * tanha(c1);
            gi = acc[4][0]; gf = acc[4][1]; gg = acc[5][0]; go = acc[5][1];
            c2 = siga(gf) * c2 + siga(gi) * tanha(gg);  h2 = siga(go) * tanha(c2);
            gi = acc[6][0]; gf = acc[6][1]; gg = acc[7][0]; go = acc[7][1];
            c3 = siga(gf) * c3 + siga(gi) * tanha(gg);  h3 = siga(go) * tanha(c3);
        }
        // fp8 h -> next buffer (kpos = wid*16 + q*4 + tp)
        *(uint32_t*)&Hsm[(t + 1) & 1][r * 144 + wid * 16 + q * 4] =
            pack_e4m3_4(h0, h1, h2, h3);
        // bf16 h -> global (hperm'd position, matches g_wemit_bf)
        {
            int trow = dir ? (Tn - 1 - t) : t;
            __nv_bfloat162 pa = __floats2bfloat162_rn(h0, h1);
            __nv_bfloat162 pb = __floats2bfloat162_rn(h2, h3);
            uint2 pk = {*(uint32_t*)&pa, *(uint32_t*)&pb};
            *(uint2*)(g_hs_bf + ((size_t)trow * Bn + b0 + r) * 256
                      + dir * 128 + wid * 16 + q * 4) = pk;
        }
        __syncthreads();
        xc0 = xn0; xc1 = xn1;
    }
}

// ================= Kernel 3: emissions via tensor cores =====================
#define ESTR 264
__global__ __launch_bounds__(128) void k_emit2(const float* __restrict__ b_emit)
{
    extern __shared__ char sm[];
    __nv_bfloat16* As = (__nv_bfloat16*)sm;                     // [64][264]
    __nv_bfloat16* Bs = (__nv_bfloat16*)(sm + 64 * ESTR * 2);   // [32][264]
    float* sbias = (float*)(sm + (64 + 32) * ESTR * 2);         // [32]

    const int tid = threadIdx.x;
    const int bt0 = blockIdx.x * 64;

    {
        int row = tid >> 1, half = tid & 1;
        const uint4* src = (const uint4*)(g_hs_bf + (size_t)(bt0 + row) * 256 + half * 128);
        uint4* dst = (uint4*)(As + row * ESTR + half * 128);
#pragma unroll
        for (int i = 0; i < 16; i++) dst[i] = src[i];
        if (tid < 64) {
            const uint4* ws = (const uint4*)(g_wemit_bf + (size_t)row * 256 + half * 128);
            uint4* wd = (uint4*)(Bs + row * ESTR + half * 128);
#pragma unroll
            for (int i = 0; i < 16; i++) wd[i] = ws[i];
        }
    }
    if (tid < 32) sbias[tid] = (tid < Kn) ? b_emit[tid] : 0.0f;
    __syncthreads();

    const int wid = tid >> 5, lane = tid & 31;
    const int lr = lane & 15, lc = lane >> 4;

    float acc[3][4];
#pragma unroll
    for (int nt = 0; nt < 3; nt++)
#pragma unroll
        for (int q = 0; q < 4; q++) acc[nt][q] = 0.0f;

#pragma unroll
    for (int kk = 0; kk < 16; kk++) {
        uint32_t a0, a1, a2, a3;
        ldm4(a0, a1, a2, a3, smaddr(As + (16 * wid + lr) * ESTR + kk * 16 + lc * 8));
        uint32_t b0[4], b1[4];
        ldm4(b0[0], b0[1], b0[2], b0[3], smaddr(Bs + lr * ESTR + kk * 16 + lc * 8));
        ldm4(b1[0], b1[1], b1[2], b1[3], smaddr(Bs + (16 + lr) * ESTR + kk * 16 + lc * 8));
        mma16816(acc[0], a0, a1, a2, a3, b0[0], b0[2]);   // n 0..7
        mma16816(acc[1], a0, a1, a2, a3, b0[1], b0[3]);   // n 8..15
        mma16816(acc[2], a0, a1, a2, a3, b1[0], b1[2]);   // n 16..23
    }

    const int r = lane >> 2;
#pragma unroll
    for (int nt = 0; nt < 3; nt++) {
#pragma unroll
        for (int q = 0; q < 4; q++) {
            int n = 8 * nt + 2 * (lane & 3) + (q & 1);
            if (n >= Kn) continue;
            int bt = bt0 + 16 * wid + r + ((q >> 1) ? 8 : 0);
            int t = bt >> 7, b = bt & 127;
            g_em[((size_t)b * Tn + t) * Kn + n] = acc[nt][q] + sbias[n];
        }
    }
}

// ================= Kernel 4: CRF (linear-domain forward), 4 batches/warp ====
__global__ void k_crf2(const int* __restrict__ tags,
                       const float* __restrict__ start_t,
                       const float* __restrict__ end_t,
                       const float* __restrict__ trans)
{
    const int lane = threadIdx.x;
    const int laneC = (lane < Kn) ? lane : 0;
    int bidx[4];
    const float* em[4];
    const int* tg[4];
#pragma unroll
    for (int q = 0; q < 4; q++) {
        bidx[q] = blockIdx.x + 32 * q;
        em[q] = g_em + (size_t)bidx[q] * Tn * Kn;
        tg[q] = tags + bidx[q] * Tn;
    }

    float T[Kn];
#pragma unroll
    for (int i = 0; i < Kn; i++)
        T[i] = (lane < Kn) ? __expf(trans[i * Kn + lane]) : 0.0f;

    float sc[4];
#pragma unroll
    for (int q = 0; q < 4; q++) {
        float s = 0.0f;
        for (int t = lane + 1; t < Tn; t += 32)
            s += trans[tg[q][t - 1] * Kn + tg[q][t]] + em[q][(size_t)t * Kn + tg[q][t]];
#pragma unroll
        for (int off = 16; off; off >>= 1) s += __shfl_xor_sync(0xffffffffu, s, off);
        s += start_t[tg[q][0]] + em[q][tg[q][0]] + end_t[tg[q][Tn - 1]];
        sc[q] = s;
    }

    float A[4], la[4], ec[4];
#pragma unroll
    for (int q = 0; q < 4; q++) {
        A[q] = (lane < Kn) ? __expf(start_t[lane] + em[q][lane]) : 0.0f;
        la[q] = 0.0f;
        ec[q] = em[q][Kn + laneC];
    }

    for (int t = 1; t < Tn; t++) {
        float en[4];
        if (t + 1 < Tn) {
#pragma unroll
            for (int q = 0; q < 4; q++) en[q] = em[q][(size_t)(t + 1) * Kn + laneC];
        }
        float s0 = 0.f, s1 = 0.f, s2 = 0.f, s3 = 0.f;
#pragma unroll
        for (int i = 0; i < Kn; i++) {
            float a0 = __shfl_sync(0xffffffffu, A[0], i);
            float a1 = __shfl_sync(0xffffffffu, A[1], i);
            float a2 = __shfl_sync(0xffffffffu, A[2], i);
            float a3 = __shfl_sync(0xffffffffu, A[3], i);
            s0 += a0 * T[i]; s1 += a1 * T[i]; s2 += a2 * T[i]; s3 += a3 * T[i];
        }
        A[0] = s0 * __expf(ec[0]);
        A[1] = s1 * __expf(ec[1]);
        A[2] = s2 * __expf(ec[2]);
        A[3] = s3 * __expf(ec[3]);
        if ((t & 3) == 3) {
#pragma unroll
            for (int q = 0; q < 4; q++) {
                float m = A[q];
#pragma unroll
                for (int off = 16; off; off >>= 1)
                    m = fmaxf(m, __shfl_xor_sync(0xffffffffu, m, off));
                la[q] += __logf(m);
                A[q] = __fdividef(A[q], m);
            }
        }
        if (t + 1 < Tn) {
#pragma unroll
            for (int q = 0; q < 4; q++) ec[q] = en[q];
        }
    }

    float Ee = (lane < Kn) ? __expf(end_t[lane]) : 0.0f;
#pragma unroll
    for (int q = 0; q < 4; q++) {
        float x = A[q] * Ee;
#pragma unroll
        for (int off = 16; off; off >>= 1) x += __shfl_xor_sync(0xffffffffu, x, off);
        float logZ = __logf(x) + la[q];
        if (lane == 0) g_llh[bidx[q]] = sc[q] - logZ;
    }
}

// ================= Kernel 5: final mean =====================================
__global__ void k_reduce(float* __restrict__ out)
{
    const int tid = threadIdx.x; // 128
    float v = g_llh[tid];
#pragma unroll
    for (int off = 16; off; off >>= 1) v += __shfl_xor_sync(0xffffffffu, v, off);
    __shared__ float s[4];
    if ((tid & 31) == 0) s[tid >> 5] = v;
    __syncthreads();
    if (tid == 0) out[0] = -(s[0] + s[1] + s[2] + s[3]) / (float)Bn;
}

// ============================================================================
extern "C" void kernel_launch(void* const* d_in, const int* in_sizes, int n_in,
                              void* d_out, int out_size)
{
    const int*   ids     = (const int*)d_in[0];
    const int*   tags    = (const int*)d_in[1];
    // d_in[2] = mask: all-true for this problem; intentionally unused.
    const float* embed   = (const float*)d_in[3];
    const float* w_ih_f  = (const float*)d_in[4];
    const float* w_hh_f  = (const float*)d_in[5];
    const float* b_ih_f  = (const float*)d_in[6];
    const float* b_hh_f  = (const float*)d_in[7];
    const float* w_ih_b  = (const float*)d_in[8];
    const float* w_hh_b  = (const float*)d_in[9];
    const float* b_ih_b  = (const float*)d_in[10];
    const float* b_hh_b  = (const float*)d_in[11];
    const float* w_emit  = (const float*)d_in[12];
    const float* b_emit  = (const float*)d_in[13];
    const float* start_t = (const float*)d_in[14];
    const float* end_t   = (const float*)d_in[15];
    const float* trans   = (const float*)d_in[16];

    const int SMEM_XP2   = 2 * 128 * ASTR * 2 + 512;          // 70,144 B
    const int SMEM_EMIT  = (64 + 32) * ESTR * 2 + 128;        // 50,816 B
    const int SMEM_LSTM7 = 512 * 144;                         // 73,728 B
    cudaFuncSetAttribute(k_xp2,   cudaFuncAttributeMaxDynamicSharedMemorySize, SMEM_XP2);
    cudaFuncSetAttribute(k_emit2, cudaFuncAttributeMaxDynamicSharedMemorySize, SMEM_EMIT);
    cudaFuncSetAttribute(k_lstm7, cudaFuncAttributeMaxDynamicSharedMemorySize, SMEM_LSTM7);

    k_cvt<<<Vn * En / 2 / 256, 256>>>(embed, w_ih_f, w_ih_b, w_hh_f, w_hh_b,
                                      b_ih_f, b_hh_f, b_ih_b, b_hh_b, w_emit);
    k_xp2<<<dim3(8, 512), 256, SMEM_XP2>>>(ids);
    k_lstm7<<<32, 256, SMEM_LSTM7>>>();
    k_emit2<<<1024, 128, SMEM_EMIT>>>(b_emit);
    k_crf2<<<32, 32>>>(tags, start_t, end_t, trans);
    k_reduce<<<1, 128>>>((float*)d_out);
}

// round 11
// speedup vs baseline: 1.0114x; 1.0114x over previous
#include <cuda_runtime.h>
#include <cuda_bf16.h>
#include <cstdint>

#define Vn 30000
#define Kn 17
#define En 128
#define Hn 128
#define Bn 128
#define Tn 512
#define G4H 512   // 4*H

// ---------------- scratch (device globals; allocation-free) ----------------
// xp stored bf16, layout [dir][t][rank][b][128] with gate-permuted last dim:
//   c = (wid'<<4) | ((gate&2)<<2) | (a<<1) | (gate&1),  j = 32*rank + 4*wid' + a
__device__ __nv_bfloat16 g_xp_bf[(size_t)2 * Tn * 4 * Bn * 128];
__device__ __nv_bfloat16 g_hs_bf[(size_t)Tn * Bn * 2 * Hn];   // [t*B+b][256]
__device__ float g_em[(size_t)Bn * Tn * Kn];                  // [b][t][k]
__device__ float g_llh[Bn];
__device__ __nv_bfloat16 g_embed_bf[(size_t)Vn * En];
__device__ __nv_bfloat16 g_wih_bf[2 * (size_t)G4H * En];      // [dir][g][k]
__device__ __nv_bfloat16 g_wemit_bf[32 * 256];                // rows>=17 zero
__device__ float g_bias[2 * G4H];

__device__ __forceinline__ float tanha(float x) {
    float r; asm("tanh.approx.f32 %0,%1;" : "=f"(r) : "f"(x)); return r;
}
__device__ __forceinline__ float siga(float x) {
    return 0.5f * tanha(0.5f * x) + 0.5f;
}

// ================= Kernel 0: fp32 -> bf16 conversions =======================
__global__ __launch_bounds__(256) void k_cvt(
    const float* __restrict__ embed,
    const float* __restrict__ wf, const float* __restrict__ wb,
    const float* __restrict__ bihf, const float* __restrict__ bhhf,
    const float* __restrict__ bihb, const float* __restrict__ bhhb,
    const float* __restrict__ w_emit)
{
    int i = blockIdx.x * 256 + threadIdx.x;
    if (i < Vn * En / 2) {
        float2 v = ((const float2*)embed)[i];
        ((__nv_bfloat162*)g_embed_bf)[i] = __floats2bfloat162_rn(v.x, v.y);
    }
    if (i < G4H * En / 2) {
        float2 v = ((const float2*)wf)[i];
        ((__nv_bfloat162*)g_wih_bf)[i] = __floats2bfloat162_rn(v.x, v.y);
        float2 u = ((const float2*)wb)[i];
        ((__nv_bfloat162*)g_wih_bf)[G4H * En / 2 + i] = __floats2bfloat162_rn(u.x, u.y);
    }
    if (i < G4H) {
        g_bias[i] = bihf[i] + bhhf[i];
        g_bias[G4H + i] = bihb[i] + bhhb[i];
    }
    if (i < 32 * 128) {   // w_emit padded to 32 rows, bf16
        int row = i >> 7, col2 = i & 127;
        __nv_bfloat162 v;
        if (row < Kn) {
            v = __floats2bfloat162_rn(w_emit[row * 256 + 2 * col2],
                                      w_emit[row * 256 + 2 * col2 + 1]);
        } else {
            v = __floats2bfloat162_rn(0.0f, 0.0f);
        }
        ((__nv_bfloat162*)g_wemit_bf)[i] = v;
    }
}

// ---------------- mma / cluster helpers ----------------
__device__ __forceinline__ uint32_t smaddr(const void* p) {
    return (uint32_t)__cvta_generic_to_shared(p);
}
__device__ __forceinline__ void ldm4(uint32_t& r0, uint32_t& r1, uint32_t& r2, uint32_t& r3, uint32_t a) {
    asm volatile("ldmatrix.sync.aligned.m8n8.x4.shared.b16 {%0,%1,%2,%3},[%4];"
                 : "=r"(r0), "=r"(r1), "=r"(r2), "=r"(r3) : "r"(a));
}
__device__ __forceinline__ void mma16816(float* c, uint32_t a0, uint32_t a1, uint32_t a2, uint32_t a3,
                                         uint32_t b0, uint32_t b1) {
    asm volatile("mma.sync.aligned.m16n8k16.row.col.f32.bf16.bf16.f32 "
                 "{%0,%1,%2,%3},{%4,%5,%6,%7},{%8,%9},{%0,%1,%2,%3};"
                 : "+f"(c[0]), "+f"(c[1]), "+f"(c[2]), "+f"(c[3])
                 : "r"(a0), "r"(a1), "r"(a2), "r"(a3), "r"(b0), "r"(b1));
}
__device__ __forceinline__ uint32_t mapa_u32(uint32_t a, uint32_t rnk) {
    uint32_t d; asm("mapa.shared::cluster.u32 %0,%1,%2;" : "=r"(d) : "r"(a), "r"(rnk));
    return d;
}
__device__ __forceinline__ void mbar_init(uint32_t bar, uint32_t cnt) {
    asm volatile("mbarrier.init.shared.b64 [%0],%1;" :: "r"(bar), "r"(cnt) : "memory");
}
__device__ __forceinline__ void mbar_expect(uint32_t bar, uint32_t tx) {
    asm volatile("mbarrier.arrive.expect_tx.shared.b64 _,[%0],%1;" :: "r"(bar), "r"(tx) : "memory");
}
__device__ __forceinline__ void mbar_wait_cluster(uint32_t bar, uint32_t parity) {
    uint32_t done;
    do {
        asm volatile("{\n\t.reg .pred p;\n\t"
                     "mbarrier.try_wait.parity.acquire.cluster.shared::cta.b64 p,[%1],%2,0x989680;\n\t"
                     "selp.b32 %0,1,0,p;\n\t}"
                     : "=r"(done) : "r"(bar), "r"(parity) : "memory");
    } while (!done);
}
// SMEM->peer-SMEM bulk copy; completion tx-bytes on the DEST CTA's mbarrier.
__device__ __forceinline__ void cp_bulk_s2s(uint32_t dst, uint32_t src, uint32_t size, uint32_t rbar) {
    asm volatile("cp.async.bulk.shared::cluster.shared::cta.mbarrier::complete_tx::bytes "
                 "[%0], [%1], %2, [%3];"
                 :: "r"(dst), "r"(src), "r"(size), "r"(rbar) : "memory");
}
__device__ __forceinline__ void fence_proxy_async_cta() {
    asm volatile("fence.proxy.async.shared::cta;" ::: "memory");
}

#define ASTR 136   // bf16 elems per smem row (128 + 8 pad: conflict-free ldmatrix)
#define HROW 80    // bytes per h row (40 bf16; 32 used) -> banks 20r%32 all-distinct
#define HBLK 1280  // 16 rows x 80 B = one rank's h block

// ================= Kernel 1: input projection (tensor cores, permuted out) ==
// grid (8, 512): x = nt (dir*4+gate), y = t.
__global__ __launch_bounds__(256) void k_xp2(const int* __restrict__ ids)
{
    extern __shared__ char sm[];
    __nv_bfloat16* As = (__nv_bfloat16*)sm;                      // [128][136]
    __nv_bfloat16* Bs = (__nv_bfloat16*)(sm + 128 * ASTR * 2);   // [128][136]
    float* sbias = (float*)(sm + 2 * 128 * ASTR * 2);            // [128]

    const int t = blockIdx.y;
    const int nt = blockIdx.x;         // 0..7
    const int dir = nt >> 2;
    const int gate = nt & 3;
    const int gBase = gate * 128;
    const int tid = threadIdx.x;

    {
        int r = tid >> 1, half = tid & 1;
        int id = ids[r * Tn + t];
        const uint4* src = (const uint4*)(g_embed_bf + (size_t)id * En + half * 64);
        uint4* dst = (uint4*)(As + r * ASTR + half * 64);
#pragma unroll
        for (int i = 0; i < 8; i++) dst[i] = src[i];
        const uint4* wsrc = (const uint4*)(g_wih_bf + ((size_t)dir * G4H + gBase + r) * En + half * 64);
        uint4* wdst = (uint4*)(Bs + r * ASTR + half * 64);
#pragma unroll
        for (int i = 0; i < 8; i++) wdst[i] = wsrc[i];
    }
    if (tid < 128) sbias[tid] = g_bias[dir * G4H + gBase + tid];
    __syncthreads();

    const int wid = tid >> 5, lane = tid & 31;
    const int wm = (wid & 3) * 32;
    const int wn = (wid >> 2) * 64;

    float acc[2][8][4];
#pragma unroll
    for (int im = 0; im < 2; im++)
#pragma unroll
        for (int inn = 0; inn < 8; inn++)
#pragma unroll
            for (int r = 0; r < 4; r++) acc[im][inn][r] = 0.0f;

    const int lr = lane & 15, lc = lane >> 4;
#pragma unroll
    for (int kk = 0; kk < 8; kk++) {
        uint32_t a[2][4];
#pragma unroll
        for (int im = 0; im < 2; im++) {
            uint32_t ad = smaddr(As + (wm + im * 16 + lr) * ASTR + kk * 16 + lc * 8);
            ldm4(a[im][0], a[im][1], a[im][2], a[im][3], ad);
        }
        uint32_t b[4][4];
#pragma unroll
        for (int np = 0; np < 4; np++) {
            uint32_t ad = smaddr(Bs + (wn + np * 16 + lr) * ASTR + kk * 16 + lc * 8);
            ldm4(b[np][0], b[np][1], b[np][2], b[np][3], ad);
        }
#pragma unroll
        for (int im = 0; im < 2; im++)
#pragma unroll
            for (int inn = 0; inn < 8; inn++) {
                int np = inn >> 1, hf = inn & 1;
                uint32_t bb0 = hf ? b[np][1] : b[np][0];
                uint32_t bb1 = hf ? b[np][3] : b[np][2];
                mma16816(acc[im][inn], a[im][0], a[im][1], a[im][2], a[im][3], bb0, bb1);
            }
    }

    // epilogue: bias, bf16, permuted scatter to [dir][trow][rank][b][c]
    const int trow = dir ? (Tn - 1 - t) : t;
#pragma unroll
    for (int im = 0; im < 2; im++)
#pragma unroll
        for (int inn = 0; inn < 8; inn++) {
            int gl = wn + inn * 8 + 2 * (lane & 3);       // j (even)
            float bx = sbias[gl], by = sbias[gl + 1];
            int rho = gl >> 5, jl = gl & 31;
            int widp = jl >> 2, aa = jl & 3;
            int cpos = (widp << 4) | ((gate & 2) << 2) | (aa << 1) | (gate & 1);
            int row0 = wm + im * 16 + (lane >> 2);
            size_t base = (((size_t)(dir * Tn + trow) * 4 + rho) * Bn) * 128;
            g_xp_bf[base + (size_t)row0 * 128 + cpos]     = __float2bfloat16(acc[im][inn][0] + bx);
            g_xp_bf[base + (size_t)row0 * 128 + cpos + 2] = __float2bfloat16(acc[im][inn][1] + by);
            g_xp_bf[base + (size_t)(row0 + 8) * 128 + cpos]     = __float2bfloat16(acc[im][inn][2] + bx);
            g_xp_bf[base + (size_t)(row0 + 8) * 128 + cpos + 2] = __float2bfloat16(acc[im][inn][3] + by);
        }
}

// ================= Kernel 2: cluster-4 j-split BiLSTM, bulk-copy exchange ===
// Cluster of 4 CTAs = one (dir, 16-batch group). CTA rank owns j-range
// [32*rank, 32*rank+32): all 4 gates (W rows permuted; each MMA fragment
// holds i,f,g,o of one (b,j) in-thread). Pointwise fully in registers.
// h exchange: epilogue stages h into Sg (exact image of this rank's block),
// __syncthreads + fence.proxy.async, then 3 threads each issue ONE
// cp.async.bulk (1280 B) to a peer's Hsm block, completing on the peer's
// mbarrier (expect_tx=3840). Own block written with plain local stores.
// Hsm is rank-major [4 blocks][16 rows][80 B]; row-start banks 20r%32 are
// all-distinct so A-ldmatrix stays conflict-free. TWO alternating barriers
// (step t uses bars[t&1], parity (t>>1)&1) keep tx attribution sound; Sg is
// double-buffered so a peer-bound copy's source read provably completes
// before the t+2 reuse.
__global__ __launch_bounds__(256, 1) __cluster_dims__(4, 1, 1)
void k_lstm8(const float* __restrict__ whhf, const float* __restrict__ whhb)
{
    __shared__ __nv_bfloat16 Wsm[128 * ASTR];
    __shared__ __align__(16) uint8_t Hsm[2][4 * HBLK];
    __shared__ __align__(16) uint8_t Sg[2][HBLK];
    __shared__ __align__(8) unsigned long long hbar_s[2];

    const int cid = blockIdx.x >> 2;
    const int rank = blockIdx.x & 3;
    const int dir = cid >> 3;
    const int b0 = (cid & 7) * 16;
    const float* whh = dir ? whhb : whhf;
    const int tid = threadIdx.x;
    const int wid = tid >> 5, lane = tid & 31;

    // ---- load my 128 permuted W_hh rows as bf16 ----
    {
        int c = tid >> 1, half = tid & 1;
        int gate = (c & 1) + 2 * ((c >> 3) & 1);
        int jl = 4 * (c >> 4) + ((c & 7) >> 1);
        int grow = gate * 128 + 32 * rank + jl;
        const float2* src = (const float2*)(whh + (size_t)grow * Hn + half * 64);
        __nv_bfloat162* dst = (__nv_bfloat162*)(Wsm + c * ASTR + half * 64);
#pragma unroll
        for (int i = 0; i < 32; i++) {
            float2 v = src[i];
            dst[i] = __floats2bfloat162_rn(v.x, v.y);
        }
    }
    for (int i = tid; i < 2 * 4 * HBLK / 4; i += 256) ((uint32_t*)Hsm)[i] = 0u;

    const uint32_t hbar0 = smaddr(&hbar_s[0]);
    const uint32_t hbar1 = smaddr(&hbar_s[1]);
    if (tid == 0) {
        mbar_init(hbar0, 1);
        mbar_init(hbar1, 1);
        mbar_expect(hbar0, 3 * HBLK);   // phase 0 of barrier 0
        mbar_expect(hbar1, 3 * HBLK);   // phase 0 of barrier 1
    }
    __syncthreads();
    asm volatile("barrier.cluster.arrive.aligned;" ::: "memory");
    asm volatile("barrier.cluster.wait.aligned;" ::: "memory");

    // ---- hoist W fragments (step-invariant) ----
    const int lr = lane & 15, lc = lane >> 4;
    uint32_t bw[8][4];
#pragma unroll
    for (int kk = 0; kk < 8; kk++)
        ldm4(bw[kk][0], bw[kk][1], bw[kk][2], bw[kk][3],
             smaddr(Wsm + (16 * wid + lr) * ASTR + kk * 16 + lc * 8));

    // ---- thread coords ----
    const int a = lane & 3, r = lane >> 2;
    const int cb = 16 * wid + 2 * a;            // xp col within rank-slice
    const int jl = 4 * wid + a;                 // local j in [0,32)
    const int destrow = (a & 1) ? (r + 8) : r;
    const int destcol = (a & 1) ? (jl - 1) : jl;   // even, local
    // own-block write pointers (local stores, no message)
    uint32_t* ownH[2];
    ownH[0] = (uint32_t*)&Hsm[0][rank * HBLK + destrow * HROW + destcol * 2];
    ownH[1] = (uint32_t*)&Hsm[1][rank * HBLK + destrow * HROW + destcol * 2];
    uint32_t* sgp[2];
    sgp[0] = (uint32_t*)&Sg[0][destrow * HROW + destcol * 2];
    sgp[1] = (uint32_t*)&Sg[1][destrow * HROW + destcol * 2];

    // sender threads (tid<3): one bulk copy each to peer p=(rank+1+tid)%4
    uint32_t dstR[2], barR[2], srcR[2];
    if (tid < 3) {
        int p = (rank + 1 + tid) & 3;
#pragma unroll
        for (int buf = 0; buf < 2; buf++) {
            dstR[buf] = mapa_u32(smaddr(&Hsm[buf][rank * HBLK]), p);
            srcR[buf] = smaddr(&Sg[buf][0]);
        }
        barR[0] = mapa_u32(hbar0, p);
        barR[1] = mapa_u32(hbar1, p);
    }

    const uint32_t* xb = (const uint32_t*)g_xp_bf
        + ((size_t)dir * Tn * 4 + rank) * Bn * 64 + (size_t)(b0 + r) * 64 + (cb >> 1);
    const size_t tstep = 4 * (size_t)Bn * 64;   // u32 per t

    const uint32_t ghs_ofs = (uint32_t)(((b0 + destrow) * 256 + dir * 128
                                         + 32 * rank + destcol) >> 1);
    uint32_t* ghs = (uint32_t*)g_hs_bf;

    uint32_t v00 = xb[0], v01 = xb[4], v10 = xb[512], v11 = xb[516];
    float creg0 = 0.0f, creg1 = 0.0f;

    for (int t = 0; t < Tn; t++) {
        uint32_t n00, n01, n10, n11;
        if (t + 1 < Tn) {
            const uint32_t* p = xb + (size_t)(t + 1) * tstep;
            n00 = p[0]; n01 = p[4]; n10 = p[512]; n11 = p[516];
        }
        // acc init from permuted xp: acc0={i,f}(r),(r+8); acc1={g,o}(r),(r+8)
        float acc0[4], acc1[4];
        {
            __nv_bfloat162 u;
            u = *(__nv_bfloat162*)&v00; acc0[0] = __bfloat162float(u.x); acc0[1] = __bfloat162float(u.y);
            u = *(__nv_bfloat162*)&v10; acc0[2] = __bfloat162float(u.x); acc0[3] = __bfloat162float(u.y);
            u = *(__nv_bfloat162*)&v01; acc1[0] = __bfloat162float(u.x); acc1[1] = __bfloat162float(u.y);
            u = *(__nv_bfloat162*)&v11; acc1[2] = __bfloat162float(u.x); acc1[3] = __bfloat162float(u.y);
        }
        // GEMM from current h buffer (rank-major blocks, 80B rows)
        const uint8_t* hb = Hsm[t & 1];
#pragma unroll
        for (int kk = 0; kk < 8; kk++) {
            uint32_t a0, a1, a2, a3;
            ldm4(a0, a1, a2, a3,
                 smaddr(hb + (kk >> 1) * HBLK + lr * HROW + (kk & 1) * 32 + lc * 16));
            mma16816(acc0, a0, a1, a2, a3, bw[kk][0], bw[kk][2]);
            mma16816(acc1, a0, a1, a2, a3, bw[kk][1], bw[kk][3]);
        }
        // pointwise in registers: (i,f,g,o) at (b=r / r+8, j)
        creg0 = siga(acc0[1]) * creg0 + siga(acc0[0]) * tanha(acc1[0]);
        float h0 = siga(acc1[1]) * tanha(creg0);
        creg1 = siga(acc0[3]) * creg1 + siga(acc0[2]) * tanha(acc1[2]);
        float h1 = siga(acc1[3]) * tanha(creg1);

        float h0p = __shfl_xor_sync(0xffffffffu, h0, 1);
        float h1p = __shfl_xor_sync(0xffffffffu, h1, 1);
        __nv_bfloat162 pk = (a & 1) ? __floats2bfloat162_rn(h1p, h1)
                                    : __floats2bfloat162_rn(h0, h0p);
        uint32_t val = *(uint32_t*)&pk;

        int trow = dir ? (Tn - 1 - t) : t;
        ghs[(uint32_t)trow * 16384 + ghs_ofs] = val;

        if (t + 1 < Tn) {
            const int bb = t & 1;               // barrier + Sg buffer this step
            const int nb = (t + 1) & 1;         // h buffer for next step
            *ownH[nb] = val;                    // own block: local store
            *sgp[bb] = val;                     // stage for peers
            __syncthreads();
            if (tid < 3) {
                fence_proxy_async_cta();
                cp_bulk_s2s(dstR[nb], srcR[bb], HBLK, barR[bb]);
            }
            mbar_wait_cluster(bb ? hbar1 : hbar0, (t >> 1) & 1);
            if (tid == 0) mbar_expect(bb ? hbar1 : hbar0, 3 * HBLK);
            v00 = n00; v01 = n01; v10 = n10; v11 = n11;
        }
    }
}

// ================= Kernel 3: emissions via tensor cores =====================
#define ESTR 264
__global__ __launch_bounds__(128) void k_emit2(const float* __restrict__ b_emit)
{
    extern __shared__ char sm[];
    __nv_bfloat16* As = (__nv_bfloat16*)sm;                     // [64][264]
    __nv_bfloat16* Bs = (__nv_bfloat16*)(sm + 64 * ESTR * 2);   // [32][264]
    float* sbias = (float*)(sm + (64 + 32) * ESTR * 2);         // [32]

    const int tid = threadIdx.x;
    const int bt0 = blockIdx.x * 64;

    {
        int row = tid >> 1, half = tid & 1;
        const uint4* src = (const uint4*)(g_hs_bf + (size_t)(bt0 + row) * 256 + half * 128);
        uint4* dst = (uint4*)(As + row * ESTR + half * 128);
#pragma unroll
        for (int i = 0; i < 16; i++) dst[i] = src[i];
        if (tid < 64) {
            const uint4* ws = (const uint4*)(g_wemit_bf + (size_t)row * 256 + half * 128);
            uint4* wd = (uint4*)(Bs + row * ESTR + half * 128);
#pragma unroll
            for (int i = 0; i < 16; i++) wd[i] = ws[i];
        }
    }
    if (tid < 32) sbias[tid] = (tid < Kn) ? b_emit[tid] : 0.0f;
    __syncthreads();

    const int wid = tid >> 5, lane = tid & 31;
    const int lr = lane & 15, lc = lane >> 4;

    float acc[3][4];
#pragma unroll
    for (int nt = 0; nt < 3; nt++)
#pragma unroll
        for (int q = 0; q < 4; q++) acc[nt][q] = 0.0f;

#pragma unroll
    for (int kk = 0; kk < 16; kk++) {
        uint32_t a0, a1, a2, a3;
        ldm4(a0, a1, a2, a3, smaddr(As + (16 * wid + lr) * ESTR + kk * 16 + lc * 8));
        uint32_t b0[4], b1[4];
        ldm4(b0[0], b0[1], b0[2], b0[3], smaddr(Bs + lr * ESTR + kk * 16 + lc * 8));
        ldm4(b1[0], b1[1], b1[2], b1[3], smaddr(Bs + (16 + lr) * ESTR + kk * 16 + lc * 8));
        mma16816(acc[0], a0, a1, a2, a3, b0[0], b0[2]);   // n 0..7
        mma16816(acc[1], a0, a1, a2, a3, b0[1], b0[3]);   // n 8..15
        mma16816(acc[2], a0, a1, a2, a3, b1[0], b1[2]);   // n 16..23
    }

    const int r = lane >> 2;
#pragma unroll
    for (int nt = 0; nt < 3; nt++) {
#pragma unroll
        for (int q = 0; q < 4; q++) {
            int n = 8 * nt + 2 * (lane & 3) + (q & 1);
            if (n >= Kn) continue;
            int bt = bt0 + 16 * wid + r + ((q >> 1) ? 8 : 0);
            int t = bt >> 7, b = bt & 127;
            g_em[((size_t)b * Tn + t) * Kn + n] = acc[nt][q] + sbias[n];
        }
    }
}

// ================= Kernel 4: CRF (linear-domain forward), 4 batches/warp ====
__global__ void k_crf2(const int* __restrict__ tags,
                       const float* __restrict__ start_t,
                       const float* __restrict__ end_t,
                       const float* __restrict__ trans)
{
    const int lane = threadIdx.x;
    const int laneC = (lane < Kn) ? lane : 0;
    int bidx[4];
    const float* em[4];
    const int* tg[4];
#pragma unroll
    for (int q = 0; q < 4; q++) {
        bidx[q] = blockIdx.x + 32 * q;
        em[q] = g_em + (size_t)bidx[q] * Tn * Kn;
        tg[q] = tags + bidx[q] * Tn;
    }

    float T[Kn];
#pragma unroll
    for (int i = 0; i < Kn; i++)
        T[i] = (lane < Kn) ? __expf(trans[i * Kn + lane]) : 0.0f;

    // ---- numerator (gold-path score): parallel over t ----
    float sc[4];
#pragma unroll
    for (int q = 0; q < 4; q++) {
        float s = 0.0f;
        for (int t = lane + 1; t < Tn; t += 32)
            s += trans[tg[q][t - 1] * Kn + tg[q][t]] + em[q][(size_t)t * Kn + tg[q][t]];
#pragma unroll
        for (int off = 16; off; off >>= 1) s += __shfl_xor_sync(0xffffffffu, s, off);
        s += start_t[tg[q][0]] + em[q][tg[q][0]] + end_t[tg[q][Tn - 1]];
        sc[q] = s;
    }

    // ---- denominator: linear-domain forward with periodic renorm ----
    float A[4], la[4], ec[4];
#pragma unroll
    for (int q = 0; q < 4; q++) {
        A[q] = (lane < Kn) ? __expf(start_t[lane] + em[q][lane]) : 0.0f;
        la[q] = 0.0f;
        ec[q] = em[q][Kn + laneC];
    }

    for (int t = 1; t < Tn; t++) {
        float en[4];
        if (t + 1 < Tn) {
#pragma unroll
            for (int q = 0; q < 4; q++) en[q] = em[q][(size_t)(t + 1) * Kn + laneC];
        }
        float s0 = 0.f, s1 = 0.f, s2 = 0.f, s3 = 0.f;
#pragma unroll
        for (int i = 0; i < Kn; i++) {
            float a0 = __shfl_sync(0xffffffffu, A[0], i);
            float a1 = __shfl_sync(0xffffffffu, A[1], i);
            float a2 = __shfl_sync(0xffffffffu, A[2], i);
            float a3 = __shfl_sync(0xffffffffu, A[3], i);
            s0 += a0 * T[i]; s1 += a1 * T[i]; s2 += a2 * T[i]; s3 += a3 * T[i];
        }
        A[0] = s0 * __expf(ec[0]);
        A[1] = s1 * __expf(ec[1]);
        A[2] = s2 * __expf(ec[2]);
        A[3] = s3 * __expf(ec[3]);
        if ((t & 3) == 3) {
#pragma unroll
            for (int q = 0; q < 4; q++) {
                float m = A[q];
#pragma unroll
                for (int off = 16; off; off >>= 1)
                    m = fmaxf(m, __shfl_xor_sync(0xffffffffu, m, off));
                la[q] += __logf(m);
                A[q] = __fdividef(A[q], m);
            }
        }
        if (t + 1 < Tn) {
#pragma unroll
            for (int q = 0; q < 4; q++) ec[q] = en[q];
        }
    }

    float Ee = (lane < Kn) ? __expf(end_t[lane]) : 0.0f;
#pragma unroll
    for (int q = 0; q < 4; q++) {
        float x = A[q] * Ee;
#pragma unroll
        for (int off = 16; off; off >>= 1) x += __shfl_xor_sync(0xffffffffu, x, off);
        float logZ = __logf(x) + la[q];
        if (lane == 0) g_llh[bidx[q]] = sc[q] - logZ;
    }
}

// ================= Kernel 5: final mean =====================================
__global__ void k_reduce(float* __restrict__ out)
{
    const int tid = threadIdx.x; // 128
    float v = g_llh[tid];
#pragma unroll
    for (int off = 16; off; off >>= 1) v += __shfl_xor_sync(0xffffffffu, v, off);
    __shared__ float s[4];
    if ((tid & 31) == 0) s[tid >> 5] = v;
    __syncthreads();
    if (tid == 0) out[0] = -(s[0] + s[1] + s[2] + s[3]) / (float)Bn;
}

// ============================================================================
extern "C" void kernel_launch(void* const* d_in, const int* in_sizes, int n_in,
                              void* d_out, int out_size)
{
    const int*   ids     = (const int*)d_in[0];
    const int*   tags    = (const int*)d_in[1];
    // d_in[2] = mask: all-true for this problem; intentionally unused.
    const float* embed   = (const float*)d_in[3];
    const float* w_ih_f  = (const float*)d_in[4];
    const float* w_hh_f  = (const float*)d_in[5];
    const float* b_ih_f  = (const float*)d_in[6];
    const float* b_hh_f  = (const float*)d_in[7];
    const float* w_ih_b  = (const float*)d_in[8];
    const float* w_hh_b  = (const float*)d_in[9];
    const float* b_ih_b  = (const float*)d_in[10];
    const float* b_hh_b  = (const float*)d_in[11];
    const float* w_emit  = (const float*)d_in[12];
    const float* b_emit  = (const float*)d_in[13];
    const float* start_t = (const float*)d_in[14];
    const float* end_t   = (const float*)d_in[15];
    const float* trans   = (const float*)d_in[16];

    const int SMEM_XP2  = 2 * 128 * ASTR * 2 + 512;          // 70,144 B
    const int SMEM_EMIT = (64 + 32) * ESTR * 2 + 128;        // 50,816 B
    cudaFuncSetAttribute(k_xp2,   cudaFuncAttributeMaxDynamicSharedMemorySize, SMEM_XP2);
    cudaFuncSetAttribute(k_emit2, cudaFuncAttributeMaxDynamicSharedMemorySize, SMEM_EMIT);

    k_cvt<<<Vn * En / 2 / 256, 256>>>(embed, w_ih_f, w_ih_b,
                                      b_ih_f, b_hh_f, b_ih_b, b_hh_b, w_emit);
    k_xp2<<<dim3(8, 512), 256, SMEM_XP2>>>(ids);
    k_lstm8<<<64, 256>>>(w_hh_f, w_hh_b);
    k_emit2<<<1024, 128, SMEM_EMIT>>>(b_emit);
    k_crf2<<<32, 32>>>(tags, start_t, end_t, trans);
    k_reduce<<<1, 128>>>((float*)d_out);
}